// round 1
// baseline (speedup 1.0000x reference)
#include <cuda_runtime.h>

#define NB 8
#define S_LEN 4096
#define D 1024
#define D4 (D / 4)          // 256 float4 per row
#define CHUNKS 128
#define ROWS_PER_CHUNK (S_LEN / CHUNKS)  // 32

// Scratch (allocation-free rule: __device__ globals)
__device__ float g_partial[NB * CHUNKS * D];  // 4 MB
__device__ float g_vsum[NB * D];
__device__ float g_tmp[NB * D];

// Stage 1: partial column-sum of V over a 32-row chunk.
// grid = (CHUNKS, NB), block = 256. Thread t owns float4 column 4t.
__global__ void __launch_bounds__(256) reduce_partial(const float4* __restrict__ V) {
    const int t = threadIdx.x;
    const int c = blockIdx.x;
    const int n = blockIdx.y;
    const float4* base =
        V + ((size_t)n * S_LEN + (size_t)c * ROWS_PER_CHUNK) * D4 + t;
    float4 acc = make_float4(0.f, 0.f, 0.f, 0.f);
#pragma unroll 8
    for (int s = 0; s < ROWS_PER_CHUNK; ++s) {
        float4 v = base[(size_t)s * D4];
        acc.x += v.x; acc.y += v.y; acc.z += v.z; acc.w += v.w;
    }
    reinterpret_cast<float4*>(g_partial)[((size_t)n * CHUNKS + c) * D4 + t] = acc;
}

// Stage 2: fold the 128 partials. grid = NB, block = 256.
__global__ void __launch_bounds__(256) reduce_final() {
    const int t = threadIdx.x;
    const int n = blockIdx.x;
    const float4* p =
        reinterpret_cast<const float4*>(g_partial) + (size_t)n * CHUNKS * D4 + t;
    float4 acc = make_float4(0.f, 0.f, 0.f, 0.f);
#pragma unroll 8
    for (int c = 0; c < CHUNKS; ++c) {
        float4 v = p[(size_t)c * D4];
        acc.x += v.x; acc.y += v.y; acc.z += v.z; acc.w += v.w;
    }
    reinterpret_cast<float4*>(g_vsum)[n * D4 + t] = acc;
}

// GEMV batch-8: out[n][j] = dot(xin[n,:], W[j,:]) + bias_scale * b[j]
// grid = D (one block per output column j), block = 256.
// stage 0: xin = g_vsum, out = g_tmp (Wv, bias_scale = S_LEN)
// stage 1: xin = g_tmp,  out = dout  (Wo, bias_scale = 1)
__global__ void __launch_bounds__(256) gemv8(const float4* __restrict__ W,
                                             const float* __restrict__ b,
                                             float bias_scale, int stage,
                                             float* __restrict__ dout) {
    const int j = blockIdx.x;
    const int t = threadIdx.x;
    const int lane = t & 31;
    const int wid = t >> 5;

    const float4* xin = reinterpret_cast<const float4*>(stage == 0 ? g_vsum : g_tmp);
    float* out = (stage == 0) ? g_tmp : dout;

    float4 w = W[(size_t)j * D4 + t];

    float p[NB];
#pragma unroll
    for (int n = 0; n < NB; ++n) {
        float4 x = xin[n * D4 + t];
        p[n] = w.x * x.x + w.y * x.y + w.z * x.z + w.w * x.w;
    }

    // warp-level reduce each of the 8 accumulators
#pragma unroll
    for (int n = 0; n < NB; ++n) {
#pragma unroll
        for (int ofs = 16; ofs > 0; ofs >>= 1)
            p[n] += __shfl_xor_sync(0xFFFFFFFFu, p[n], ofs);
    }

    __shared__ float sw[8][NB];  // [warp][n]
    if (lane == 0) {
#pragma unroll
        for (int n = 0; n < NB; ++n) sw[wid][n] = p[n];
    }
    __syncthreads();

    if (t < NB) {  // thread t finalizes batch index n = t
        float s = 0.f;
#pragma unroll
        for (int w2 = 0; w2 < 8; ++w2) s += sw[w2][t];
        out[t * D + j] = s + bias_scale * b[j];
    }
}

extern "C" void kernel_launch(void* const* d_in, const int* in_sizes, int n_in,
                              void* d_out, int out_size) {
    (void)in_sizes; (void)n_in; (void)out_size;
    // metadata order: Q(0) K(1) V(2) Wq(3) bq(4) Wk(5) bk(6) Wv(7) bv(8) Wo(9) bo(10)
    // softmax over a size-1 axis == 1.0 -> Q, K, Wq, bq, Wk, bk are dead.
    const float4* V  = (const float4*)d_in[2];
    const float4* Wv = (const float4*)d_in[7];
    const float*  bv = (const float*)d_in[8];
    const float4* Wo = (const float4*)d_in[9];
    const float*  bo = (const float*)d_in[10];
    float* out = (float*)d_out;

    reduce_partial<<<dim3(CHUNKS, NB), 256>>>(V);
    reduce_final<<<NB, 256>>>();
    gemv8<<<D, 256>>>(Wv, bv, (float)S_LEN, 0, nullptr);
    gemv8<<<D, 256>>>(Wo, bo, 1.0f, 1, out);
}